// round 1
// baseline (speedup 1.0000x reference)
#include <cuda_runtime.h>

#define N_ROWS 8000
#define D 9
#define N4 2000           // N_ROWS / 4
#define OUT_TPB 256
#define ROWS_PER_BLK 8
#define SCAN_TPB 1024
#define SCAN_RPT 8        // 1000 active threads * 8 rows = 8000

// Scratch (device globals — no allocation allowed)
__device__ float d_t1[N_ROWS];
__device__ float d_t2[N_ROWS];
__device__ float d_g[N_ROWS];
__device__ float d_h[N_ROWS];
__device__ float d_w1bar[N_ROWS];

// ---------------------------------------------------------------------------
// Kernel 1: per-row stats.  t1[r] = sum_d ((x-c1)/a1)^2  (log-domain membership)
//           g[r] = f1[r]-f2[r],  h[r] = f2[r]
// ---------------------------------------------------------------------------
__global__ void k_rowstats(const float* __restrict__ x,
                           const float* __restrict__ a1, const float* __restrict__ c1,
                           const float* __restrict__ a2, const float* __restrict__ c2,
                           const float* __restrict__ wf1, const float* __restrict__ bf1,
                           const float* __restrict__ wf2, const float* __restrict__ bf2)
{
    int r = blockIdx.x * blockDim.x + threadIdx.x;
    if (r >= N_ROWS) return;

    const float C1 = c1[0], C2 = c2[0];
    const float inv1 = 1.0f / a1[0];
    const float inv2 = 1.0f / a2[0];

    float s1 = 0.0f, s2 = 0.0f;
    float f1 = bf1[0], f2 = bf2[0];

#pragma unroll
    for (int d = 0; d < D; d++) {
        float xv = x[r * D + d];
        float u1 = (xv - C1) * inv1;
        float u2 = (xv - C2) * inv2;
        s1 = fmaf(u1, u1, s1);
        s2 = fmaf(u2, u2, s2);
        f1 = fmaf(xv, wf1[d], f1);
        f2 = fmaf(xv, wf2[d], f2);
    }
    d_t1[r] = s1;
    d_t2[r] = s2;
    d_g[r]  = f1 - f2;
    d_h[r]  = f2;
}

// ---------------------------------------------------------------------------
// Kernel 2: single-block cumsum over 8000 rows of (t1, t2);
//           w1bar[r] = 1 / (1 + exp(S1[r] - S2[r]))
// Thread t owns rows [t*8, t*8+8). Local inclusive cumsum, block scan of
// thread totals (Hillis-Steele in shared), add exclusive offset.
// ---------------------------------------------------------------------------
__global__ void k_scan()
{
    __shared__ float sh1[SCAN_TPB];
    __shared__ float sh2[SCAN_TPB];
    const int t = threadIdx.x;
    const bool active = (t * SCAN_RPT) < N_ROWS;   // threads 0..999

    float v1[SCAN_RPT], v2[SCAN_RPT];
    float acc1 = 0.0f, acc2 = 0.0f;

    if (active) {
        const float4* p1 = reinterpret_cast<const float4*>(d_t1) + t * 2;
        const float4* p2 = reinterpret_cast<const float4*>(d_t2) + t * 2;
        float4 q0 = p1[0], q1 = p1[1];
        float4 r0 = p2[0], r1 = p2[1];
        float b1[SCAN_RPT] = {q0.x, q0.y, q0.z, q0.w, q1.x, q1.y, q1.z, q1.w};
        float b2[SCAN_RPT] = {r0.x, r0.y, r0.z, r0.w, r1.x, r1.y, r1.z, r1.w};
#pragma unroll
        for (int k = 0; k < SCAN_RPT; k++) {
            acc1 += b1[k]; v1[k] = acc1;
            acc2 += b2[k]; v2[k] = acc2;
        }
    }
    sh1[t] = acc1;
    sh2[t] = acc2;
    __syncthreads();

    // Hillis-Steele inclusive scan over thread totals
    for (int ofs = 1; ofs < SCAN_TPB; ofs <<= 1) {
        float x1 = (t >= ofs) ? sh1[t - ofs] : 0.0f;
        float x2 = (t >= ofs) ? sh2[t - ofs] : 0.0f;
        __syncthreads();
        sh1[t] += x1;
        sh2[t] += x2;
        __syncthreads();
    }

    if (active) {
        float off1 = (t > 0) ? sh1[t - 1] : 0.0f;
        float off2 = (t > 0) ? sh2[t - 1] : 0.0f;
        float w[SCAN_RPT];
#pragma unroll
        for (int k = 0; k < SCAN_RPT; k++) {
            float S1 = off1 + v1[k];
            float S2 = off2 + v2[k];
            w[k] = 1.0f / (1.0f + expf(S1 - S2));   // = w1 / (w1 + w2)
        }
        float4* pw = reinterpret_cast<float4*>(d_w1bar) + t * 2;
        pw[0] = make_float4(w[0], w[1], w[2], w[3]);
        pw[1] = make_float4(w[4], w[5], w[6], w[7]);
    }
}

// ---------------------------------------------------------------------------
// Kernel 3: out[i, j] = h[i] + g[i] * w1bar[j]   (256 MB of stores — the cost)
// Each thread owns one float4 of columns and loops over 8 rows.
// ---------------------------------------------------------------------------
__global__ void k_outer(float* __restrict__ out)
{
    int j4 = blockIdx.x * OUT_TPB + threadIdx.x;
    if (j4 >= N4) return;

    float4 w4 = reinterpret_cast<const float4*>(d_w1bar)[j4];
    int i0 = blockIdx.y * ROWS_PER_BLK;
    float4* o4 = reinterpret_cast<float4*>(out);

#pragma unroll
    for (int k = 0; k < ROWS_PER_BLK; k++) {
        int i = i0 + k;
        float gv = d_g[i];
        float hv = d_h[i];
        float4 o;
        o.x = fmaf(gv, w4.x, hv);
        o.y = fmaf(gv, w4.y, hv);
        o.z = fmaf(gv, w4.z, hv);
        o.w = fmaf(gv, w4.w, hv);
        o4[(size_t)i * N4 + j4] = o;
    }
}

// ---------------------------------------------------------------------------
extern "C" void kernel_launch(void* const* d_in, const int* in_sizes, int n_in,
                              void* d_out, int out_size)
{
    const float* x   = (const float*)d_in[0];
    const float* a1  = (const float*)d_in[1];
    const float* c1  = (const float*)d_in[2];
    const float* a2  = (const float*)d_in[3];
    const float* c2  = (const float*)d_in[4];
    const float* wf1 = (const float*)d_in[5];
    const float* bf1 = (const float*)d_in[6];
    const float* wf2 = (const float*)d_in[7];
    const float* bf2 = (const float*)d_in[8];
    float* out = (float*)d_out;

    k_rowstats<<<(N_ROWS + 127) / 128, 128>>>(x, a1, c1, a2, c2, wf1, bf1, wf2, bf2);
    k_scan<<<1, SCAN_TPB>>>();

    dim3 grid((N4 + OUT_TPB - 1) / OUT_TPB, N_ROWS / ROWS_PER_BLK);  // (8, 1000)
    k_outer<<<grid, OUT_TPB>>>(out);
}